// round 11
// baseline (speedup 1.0000x reference)
#include <cuda_runtime.h>

// SmoothAPLoss via dual-histogram dot product, single fused kernel.
//   c_i = p_pos_i - DELTA ; bins b = clamp((int)(x*NB)) over x in (0,1)
//   total = sum_b [ pcnt[b]*ssum[b] - scnt[b]*psum[b] ],  ssum/scnt = inclusive
//   suffix sums of negative-histogram (sum, count); npos = sum_b pcnt[b].
// Identical to per-positive lookup (bin members share the lookup). Last block
// (done-counter) computes the reduction; all state self-cleans for graph replay.

#define DELTA 0.01f
#define NB    4096
#define TPB   512
#define BPT   (NB / TPB)     // 8 bins per thread in finish phase

__device__ __align__(16) float g_ncnt[NB];
__device__ __align__(16) float g_nsum[NB];
__device__ __align__(16) float g_pcnt[NB];
__device__ __align__(16) float g_psum[NB];
__device__ int g_done;

__device__ __forceinline__ float warp_suffix_incl(float v, int lane) {
#pragma unroll
    for (int off = 1; off < 32; off <<= 1) {
        float o = __shfl_down_sync(0xFFFFFFFFu, v, off);
        if (lane + off < 32) v += o;
    }
    return v;
}

__global__ void __launch_bounds__(TPB)
fused_kernel(const float2* __restrict__ pred, const int* __restrict__ lab,
             int n, float* __restrict__ out) {
    const int tid = threadIdx.x;
    const int lane = tid & 31;
    const int wid = tid >> 5;

    // ---- phase 1: sigmoid + dual histogram (spread REDG atomics) ----
    int i = blockIdx.x * TPB + tid;
    if (i < n) {
        float2 x = pred[i];
        float p = 1.0f / (1.0f + __expf(x.x - x.y));
        if (lab[i] == 1) {
            float c = p - DELTA;
            int b = max(0, min((int)(c * (float)NB), NB - 1));
            atomicAdd(&g_pcnt[b], 1.0f);
            atomicAdd(&g_psum[b], c);
        } else {
            int b = max(0, min((int)(p * (float)NB), NB - 1));
            atomicAdd(&g_ncnt[b], 1.0f);
            atomicAdd(&g_nsum[b], p);
        }
    }

    // ---- done-counter: last block performs the reduction ----
    __threadfence();
    __syncthreads();
    __shared__ int s_last;
    if (tid == 0)
        s_last = (atomicAdd(&g_done, 1) == (int)gridDim.x - 1) ? 1 : 0;
    __syncthreads();
    if (!s_last) return;

    // ---- phase 2 (last block only): scan + dot product over NB bins ----
    __shared__ float wtc[32], wts[32], wtp[32];
    __shared__ double wred[TPB / 32];
    __shared__ float s_npos;

    const int base = tid * BPT;

    // load own 8 bins of each array with L2 (.cg) loads — bypass stale L1
    float nc[BPT], ns[BPT], pc[BPT], ps[BPT];
#pragma unroll
    for (int j = 0; j < BPT; j += 4) {
        float4 a = __ldcg((const float4*)&g_ncnt[base + j]);
        float4 b = __ldcg((const float4*)&g_nsum[base + j]);
        float4 c = __ldcg((const float4*)&g_pcnt[base + j]);
        float4 d = __ldcg((const float4*)&g_psum[base + j]);
        nc[j] = a.x; nc[j+1] = a.y; nc[j+2] = a.z; nc[j+3] = a.w;
        ns[j] = b.x; ns[j+1] = b.y; ns[j+2] = b.z; ns[j+3] = b.w;
        pc[j] = c.x; pc[j+1] = c.y; pc[j+2] = c.z; pc[j+3] = c.w;
        ps[j] = d.x; ps[j+1] = d.y; ps[j+2] = d.z; ps[j+3] = d.w;
    }
    // self-clean for next graph replay
    float4 z = make_float4(0.f, 0.f, 0.f, 0.f);
#pragma unroll
    for (int j = 0; j < BPT; j += 4) {
        *(float4*)&g_ncnt[base + j] = z;
        *(float4*)&g_nsum[base + j] = z;
        *(float4*)&g_pcnt[base + j] = z;
        *(float4*)&g_psum[base + j] = z;
    }

    float ct = 0.f, st = 0.f, pt = 0.f;
#pragma unroll
    for (int j = 0; j < BPT; j++) { ct += nc[j]; st += ns[j]; pt += pc[j]; }

    // warp-level inclusive suffix scans of thread totals (+ pt plain sum)
    float ic = warp_suffix_incl(ct, lane);
    float is = warp_suffix_incl(st, lane);
    float ip = warp_suffix_incl(pt, lane);     // lane 0 holds warp total
    if (lane == 0) { wtc[wid] = ic; wts[wid] = is; wtp[wid] = ip; }
    __syncthreads();

    // warp 0: strictly-above suffix over the warp totals (TPB/32 = 16 warps)
    if (wid == 0) {
        float c2 = (lane < TPB / 32) ? wtc[lane] : 0.0f;
        float s2 = (lane < TPB / 32) ? wts[lane] : 0.0f;
        float p2 = (lane < TPB / 32) ? wtp[lane] : 0.0f;
        float c2i = warp_suffix_incl(c2, lane);
        float s2i = warp_suffix_incl(s2, lane);
        float p2i = warp_suffix_incl(p2, lane);
        if (lane < TPB / 32) { wtc[lane] = c2i - c2; wts[lane] = s2i - s2; }
        if (lane == 0) s_npos = p2i;           // total positives
    }
    if (tid == 0) g_done = 0;                  // self-clean counter
    __syncthreads();

    // per-thread descending pass: running inclusive suffix + dot terms
    float runc = (ic - ct) + wtc[wid];
    float runs = (is - st) + wts[wid];
    float a = 0.0f;
#pragma unroll
    for (int j = BPT - 1; j >= 0; j--) {
        runc += nc[j];
        runs += ns[j];
        a += pc[j] * runs - runc * ps[j];
    }

    // block reduce: fp32 within warp, double across 16 warp sums
    for (int off = 16; off > 0; off >>= 1)
        a += __shfl_down_sync(0xFFFFFFFFu, a, off);
    if (lane == 0) wred[wid] = (double)a;
    __syncthreads();
    if (tid == 0) {
        double t = 0.0;
#pragma unroll
        for (int w = 0; w < TPB / 32; w++) t += wred[w];
        double denom = (double)fmaxf(s_npos, 1.0f);
        out[0] = (float)(t / denom);
    }
}

extern "C" void kernel_launch(void* const* d_in, const int* in_sizes, int n_in,
                              void* d_out, int out_size) {
    const float2* pred = (const float2*)d_in[0];
    const int* lab = (const int*)d_in[1];
    float* out = (float*)d_out;
    int n = in_sizes[1];

    int nblk = (n + TPB - 1) / TPB;   // 32 for N=16384
    fused_kernel<<<nblk, TPB>>>(pred, lab, n, out);
}

// round 12
// speedup vs baseline: 1.2071x; 1.2071x over previous
#include <cuda_runtime.h>

// SmoothAPLoss via dual-histogram dot product, single fused kernel.
//   c_i = p_pos_i - DELTA ; bins b = clamp((int)(x*NB)) over x in (0,1)
//   total = sum_b [ pcnt[b]*ssum[b] - scnt[b]*psum[b] ],  ssum/scnt = inclusive
//   suffix sums of the negative histogram; npos = sum_b pcnt[b].
// Last block (done-counter) runs the reduction tail. NB=1024 keeps the tail's
// serial chain short (16KB L2 load, 2 bins/thread); quantization error ~1e-5,
// two orders under the 1e-3 threshold. All state self-cleans for graph replay.

#define DELTA 0.01f
#define NB    1024
#define TPB   512
#define BPT   (NB / TPB)     // 2 bins per thread in the tail

__device__ __align__(16) float g_ncnt[NB];
__device__ __align__(16) float g_nsum[NB];
__device__ __align__(16) float g_pcnt[NB];
__device__ __align__(16) float g_psum[NB];
__device__ int g_done;

__device__ __forceinline__ float warp_suffix_incl(float v, int lane) {
#pragma unroll
    for (int off = 1; off < 32; off <<= 1) {
        float o = __shfl_down_sync(0xFFFFFFFFu, v, off);
        if (lane + off < 32) v += o;
    }
    return v;
}

__global__ void __launch_bounds__(TPB)
fused_kernel(const float2* __restrict__ pred, const int* __restrict__ lab,
             int n, float* __restrict__ out) {
    const int tid = threadIdx.x;
    const int lane = tid & 31;
    const int wid = tid >> 5;

    // ---- phase 1: sigmoid + dual histogram (spread REDG atomics) ----
    int i = blockIdx.x * TPB + tid;
    if (i < n) {
        float2 x = pred[i];
        float p = __fdividef(1.0f, 1.0f + __expf(x.x - x.y));
        if (lab[i] == 1) {
            float c = p - DELTA;
            int b = max(0, min((int)(c * (float)NB), NB - 1));
            atomicAdd(&g_pcnt[b], 1.0f);
            atomicAdd(&g_psum[b], c);
        } else {
            int b = max(0, min((int)(p * (float)NB), NB - 1));
            atomicAdd(&g_ncnt[b], 1.0f);
            atomicAdd(&g_nsum[b], p);
        }
    }

    // ---- done-counter: last block performs the reduction ----
    __threadfence();
    __syncthreads();
    __shared__ int s_last;
    if (tid == 0)
        s_last = (atomicAdd(&g_done, 1) == (int)gridDim.x - 1) ? 1 : 0;
    __syncthreads();
    if (!s_last) return;

    // ---- tail (last block only): scan + dot product over NB bins ----
    __shared__ float wtc[32], wts[32], wtp[32];
    __shared__ double wred[TPB / 32];
    __shared__ float s_npos;

    const int base = tid * BPT;

    // 2 bins per thread: one float2 per array, L2 (.cg) loads
    float2 a2 = __ldcg((const float2*)&g_ncnt[base]);
    float2 b2 = __ldcg((const float2*)&g_nsum[base]);
    float2 c2 = __ldcg((const float2*)&g_pcnt[base]);
    float2 d2 = __ldcg((const float2*)&g_psum[base]);
    float nc[BPT] = {a2.x, a2.y};
    float ns[BPT] = {b2.x, b2.y};
    float pc[BPT] = {c2.x, c2.y};
    float ps[BPT] = {d2.x, d2.y};

    // self-clean for next graph replay
    float2 z2 = make_float2(0.f, 0.f);
    *(float2*)&g_ncnt[base] = z2;
    *(float2*)&g_nsum[base] = z2;
    *(float2*)&g_pcnt[base] = z2;
    *(float2*)&g_psum[base] = z2;

    float ct = nc[0] + nc[1];
    float st = ns[0] + ns[1];
    float pt = pc[0] + pc[1];

    // warp-level inclusive suffix scans of thread totals
    float ic = warp_suffix_incl(ct, lane);
    float is = warp_suffix_incl(st, lane);
    float ip = warp_suffix_incl(pt, lane);     // lane 0 = warp total
    if (lane == 0) { wtc[wid] = ic; wts[wid] = is; wtp[wid] = ip; }
    __syncthreads();

    // warp 0: strictly-above suffix over the 16 warp totals
    if (wid == 0) {
        float cc = (lane < TPB / 32) ? wtc[lane] : 0.0f;
        float ss = (lane < TPB / 32) ? wts[lane] : 0.0f;
        float pp = (lane < TPB / 32) ? wtp[lane] : 0.0f;
        float cci = warp_suffix_incl(cc, lane);
        float ssi = warp_suffix_incl(ss, lane);
        float ppi = warp_suffix_incl(pp, lane);
        if (lane < TPB / 32) { wtc[lane] = cci - cc; wts[lane] = ssi - ss; }
        if (lane == 0) s_npos = ppi;
    }
    if (tid == 0) g_done = 0;                  // self-clean counter
    __syncthreads();

    // descending pass: running inclusive suffix + dot terms
    float runc = (ic - ct) + wtc[wid];
    float runs = (is - st) + wts[wid];
    float a = 0.0f;
#pragma unroll
    for (int j = BPT - 1; j >= 0; j--) {
        runc += nc[j];
        runs += ns[j];
        a += pc[j] * runs - runc * ps[j];
    }

    // block reduce: fp32 within warp, double across 16 warp sums
    for (int off = 16; off > 0; off >>= 1)
        a += __shfl_down_sync(0xFFFFFFFFu, a, off);
    if (lane == 0) wred[wid] = (double)a;
    __syncthreads();
    if (tid == 0) {
        double t = 0.0;
#pragma unroll
        for (int w = 0; w < TPB / 32; w++) t += wred[w];
        double denom = (double)fmaxf(s_npos, 1.0f);
        out[0] = (float)(t / denom);
    }
}

extern "C" void kernel_launch(void* const* d_in, const int* in_sizes, int n_in,
                              void* d_out, int out_size) {
    const float2* pred = (const float2*)d_in[0];
    const int* lab = (const int*)d_in[1];
    float* out = (float*)d_out;
    int n = in_sizes[1];

    int nblk = (n + TPB - 1) / TPB;   // 32 for N=16384
    fused_kernel<<<nblk, TPB>>>(pred, lab, n, out);
}